// round 1
// baseline (speedup 1.0000x reference)
#include <cuda_runtime.h>
#include <cstdint>

// DepthAwareConv2d: out = conv3x3(x * depth, W) + bias
// N=4, C=128, O=256, H=W=128, K=3, pad=1, stride=1, fp32.
//
// Identity used: unfold(x)*unfold(depth) taps read the SAME input pixel, so
// the depth modulation is an elementwise pre-scale of x (broadcast over C).

#define Nn 4
#define Cc 128
#define Oo 256
#define Hh 128
#define Ww 128
#define TH 16
#define TW 16
#define TO 64
#define CCH 4                  // input channels staged per chunk
#define NCHUNK (Cc / CCH)

__device__ __forceinline__ float2 ffma2(float2 a, float2 b, float2 c) {
    float2 d;
    asm("fma.rn.f32x2 %0, %1, %2, %3;"
        : "=l"(reinterpret_cast<unsigned long long&>(d))
        : "l"(reinterpret_cast<unsigned long long&>(a)),
          "l"(reinterpret_cast<unsigned long long&>(b)),
          "l"(reinterpret_cast<unsigned long long&>(c)));
    return d;
}

__global__ __launch_bounds__(256, 2)
void depth_conv3x3_kernel(const float* __restrict__ x,
                          const float* __restrict__ dep,
                          const float* __restrict__ w,
                          const float* __restrict__ bias,
                          float* __restrict__ out)
{
    __shared__ __align__(16) float  sD[18][20];           // depth tile (halo)
    __shared__ __align__(16) float  sX[CCH][18][20];      // x*d tile per c-chunk
    __shared__ __align__(16) float2 sW[TO][CCH][9];       // weights, duplicated (w,w)

    const int tid   = threadIdx.x;
    const int tileY = (blockIdx.x >> 3) * TH;
    const int tileX = (blockIdx.x & 7) * TW;
    const int oBase = blockIdx.y * TO;
    const int n     = blockIdx.z;

    // ---- stage depth tile once (18x18 with halo, zero-padded) ----
    for (int idx = tid; idx < 18 * 18; idx += 256) {
        const int ly = idx / 18, lx = idx - ly * 18;
        const int gy = tileY - 1 + ly, gx = tileX - 1 + lx;
        float v = 0.0f;
        if (gy >= 0 && gy < Hh && gx >= 0 && gx < Ww)
            v = dep[(n * Hh + gy) * Ww + gx];
        sD[ly][lx] = v;
    }

    // thread -> (o-group, 2x2 pixel tile)
    const int og  = tid >> 6;          // 0..3, warp-uniform
    const int pos = tid & 63;
    const int py  = (pos >> 3) << 1;   // 0,2,...,14
    const int px  = (pos & 7) << 1;    // 0,2,...,14
    const int oL  = og * 16;           // local o base (16 o's per thread)

    float2 acc[16][2];                 // [o][out-row], float2 = pixel pair
    #pragma unroll
    for (int o = 0; o < 16; o++) {
        acc[o][0] = make_float2(0.0f, 0.0f);
        acc[o][1] = make_float2(0.0f, 0.0f);
    }

    for (int ch = 0; ch < NCHUNK; ch++) {
        const int cb = ch * CCH;
        __syncthreads();

        // ---- stage x*d (CCH x 18 x 18, zero-padded halo) ----
        for (int idx = tid; idx < CCH * 324; idx += 256) {
            const int c   = idx / 324;
            const int rem = idx - c * 324;
            const int ly  = rem / 18, lx = rem - ly * 18;
            const int gy  = tileY - 1 + ly, gx = tileX - 1 + lx;
            float v = 0.0f;
            if (gy >= 0 && gy < Hh && gx >= 0 && gx < Ww)
                v = x[(((n * Cc) + cb + c) * Hh + gy) * Ww + gx] * sD[ly][lx];
            sX[c][ly][lx] = v;
        }

        // ---- stage weights, duplicated into both float2 lanes ----
        for (int idx = tid; idx < TO * CCH * 9; idx += 256) {
            const int o   = idx / (CCH * 9);
            const int rem = idx - o * (CCH * 9);
            const int c   = rem / 9, p = rem - c * 9;
            const float wv = w[(oBase + o) * (Cc * 9) + (cb + c) * 9 + p];
            sW[o][c][p] = make_float2(wv, wv);
        }
        __syncthreads();

        // ---- compute ----
        #pragma unroll
        for (int c = 0; c < CCH; c++) {
            float2 A[4], B[4], M[4];   // 4 input rows, cols [px..px+3]
            #pragma unroll
            for (int r = 0; r < 4; r++) {
                A[r] = *reinterpret_cast<const float2*>(&sX[c][py + r][px]);
                B[r] = *reinterpret_cast<const float2*>(&sX[c][py + r][px + 2]);
                M[r] = make_float2(A[r].y, B[r].x);
            }
            #pragma unroll
            for (int i = 0; i < 3; i++) {
                #pragma unroll
                for (int j = 0; j < 3; j++) {
                    const float2 xt = (j == 0) ? A[i]     : (j == 1) ? M[i]     : B[i];
                    const float2 xb = (j == 0) ? A[i + 1] : (j == 1) ? M[i + 1] : B[i + 1];
                    #pragma unroll
                    for (int o = 0; o < 16; o++) {
                        const float2 wv = sW[oL + o][c][i * 3 + j];
                        acc[o][0] = ffma2(wv, xt, acc[o][0]);
                        acc[o][1] = ffma2(wv, xb, acc[o][1]);
                    }
                }
            }
        }
    }

    // ---- epilogue: add bias, store float2 ----
    #pragma unroll
    for (int o = 0; o < 16; o++) {
        const float bv = bias[oBase + oL + o];
        #pragma unroll
        for (int r = 0; r < 2; r++) {
            float2 v = acc[o][r];
            v.x += bv; v.y += bv;
            const size_t off =
                ((size_t)((n * Oo + oBase + oL + o) * Hh + (tileY + py + r))) * Ww
                + (tileX + px);
            *reinterpret_cast<float2*>(&out[off]) = v;
        }
    }
}

extern "C" void kernel_launch(void* const* d_in, const int* in_sizes, int n_in,
                              void* d_out, int out_size)
{
    const float* x    = (const float*)d_in[0];
    const float* dep  = (const float*)d_in[1];
    // d_in[2] = camera_params (unused by the reference math)
    const float* w    = (const float*)d_in[3];
    const float* bias = (const float*)d_in[4];
    float* out = (float*)d_out;

    dim3 grid((Hh / TH) * (Ww / TW), Oo / TO, Nn);   // (64, 4, 4)
    depth_conv3x3_kernel<<<grid, 256>>>(x, dep, w, bias, out);
}